// round 4
// baseline (speedup 1.0000x reference)
#include <cuda_runtime.h>

typedef unsigned long long u64t;

__device__ __forceinline__ u64t fma2(u64t a, u64t b, u64t c) {
    u64t d;
    asm("fma.rn.f32x2 %0, %1, %2, %3;" : "=l"(d) : "l"(a), "l"(b), "l"(c));
    return d;
}
__device__ __forceinline__ u64t pk2(float lo, float hi) {
    u64t d;
    asm("mov.b64 %0, {%1, %2};" : "=l"(d) : "f"(lo), "f"(hi));
    return d;
}
__device__ __forceinline__ void unpk(u64t v, float& lo, float& hi) {
    asm("mov.b64 {%0, %1}, %2;" : "=f"(lo), "=f"(hi) : "l"(v));
}
__device__ __forceinline__ float fsqrt_ap(float x) {
    float y;
    asm("sqrt.approx.f32 %0, %1;" : "=f"(y) : "f"(x));
    return y;
}

// ---- weight region (u64t units). Each u64 = (w[2p], w[2p+1]) row pair ----
#define OW1 0
#define OW2 4560
#define OW0 6000
#define OB1 6864
#define OB0 7104
#define SM_U64 7107            // 56856 bytes of weights

// ---- stash: [288 features][129] floats (odd stride -> conflict-free lane reads) ----
#define STASH_STRIDE 129
#define STASH_WORDS  (288 * STASH_STRIDE)   // 37152 words = 148608 B
#define SMEM_BYTES   (SM_U64 * 8 + STASH_WORDS * 4)   // 205464 B

template<int J, int PS, int WS>
__device__ __forceinline__ void do_joint(
    const float* __restrict__ stash, int tid,
    float* __restrict__ ob, const u64t* __restrict__ sm,
    u64t (&fslot)[4][3], float (&jx)[4], float (&jy)[4], float (&jz)[4],
    const u64t (&g)[3])
{
    float xs[20];
#pragma unroll
    for (int i = 0; i < 9; ++i) xs[i] = stash[(J*9 + i)*STASH_STRIDE + tid];
    float jxv = stash[(216 + J*3 + 0)*STASH_STRIDE + tid];
    float jyv = stash[(216 + J*3 + 1)*STASH_STRIDE + tid];
    float jzv = stash[(216 + J*3 + 2)*STASH_STRIDE + tid];
    xs[9] = jxv; xs[10] = jyv; xs[11] = jzv;

    float dx, dy, dz;
    if (PS < 0) { dx = jxv; dy = jyv; dz = jzv; }
    else {
        const int P = (PS < 0) ? 0 : PS;
        dx = jxv - jx[P]; dy = jyv - jy[P]; dz = jzv - jz[P];
    }
    xs[12] = fsqrt_ap(dx*dx + dy*dy + dz*dz);
    jx[WS] = jxv; jy[WS] = jyv; jz[WS] = jzv;

    if (PS < 0) {
        unpk(g[0], xs[13], xs[14]); unpk(g[1], xs[15], xs[16]); unpk(g[2], xs[17], xs[18]);
    } else {
        const int P = (PS < 0) ? 0 : PS;
        unpk(fslot[P][0], xs[13], xs[14]);
        unpk(fslot[P][1], xs[15], xs[16]);
        unpk(fslot[P][2], xs[17], xs[18]);
    }
    xs[19] = 0.f;

    // layer 1: h (10 row-pairs) = W1[j] @ x + b1[j]
    u64t h[10];
    {
        const ulonglong2* bb = (const ulonglong2*)(sm + OB1 + J*10);
#pragma unroll
        for (int r = 0; r < 5; ++r) { ulonglong2 t = bb[r]; h[2*r] = t.x; h[2*r+1] = t.y; }
    }
#pragma unroll
    for (int k = 0; k < 19; ++k) {
        u64t xx = pk2(xs[k], xs[k]);
        const ulonglong2* wr = (const ulonglong2*)(sm + OW1 + (J*19 + k)*10);
#pragma unroll
        for (int r = 0; r < 5; ++r) {
            ulonglong2 w = wr[r];
            h[2*r]   = fma2(xx, w.x, h[2*r]);
            h[2*r+1] = fma2(xx, w.y, h[2*r+1]);
        }
    }

    float hs[20];
#pragma unroll
    for (int r = 0; r < 10; ++r) {
        float a, b; unpk(h[r], a, b);
        hs[2*r]   = fmaxf(a, 0.f);
        hs[2*r+1] = fmaxf(b, 0.f);
    }
    hs[19] = 1.0f;   // feeds b2 row (k=19) of sW2

    // layer 2: o (3 d-pairs) = W2[j] @ h (+ b2 via k=19 row)
    u64t o[3];
    o[0] = 0ull; o[1] = 0ull; o[2] = 0ull;
#pragma unroll
    for (int kp = 0; kp < 10; ++kp) {
        const int k0 = 2*kp;
        const ulonglong2* wp = (const ulonglong2*)(sm + OW2 + (J*20 + k0)*3);
        ulonglong2 p0 = wp[0], p1 = wp[1], p2 = wp[2];
        u64t x0 = pk2(hs[k0], hs[k0]);
        u64t x1 = pk2(hs[k0+1], hs[k0+1]);
        o[0] = fma2(x0, p0.x, o[0]);
        o[1] = fma2(x0, p0.y, o[1]);
        o[2] = fma2(x0, p1.x, o[2]);
        o[0] = fma2(x1, p1.y, o[0]);
        o[1] = fma2(x1, p2.x, o[1]);
        o[2] = fma2(x1, p2.y, o[2]);
    }

    fslot[WS][0] = o[0]; fslot[WS][1] = o[1]; fslot[WS][2] = o[2];
    u64t* ow = (u64t*)(ob + J*6);
    ow[0] = o[0]; ow[1] = o[1]; ow[2] = o[2];
}

__global__ void __launch_bounds__(128, 1)
pose_kernel(const float* __restrict__ rots, const float* __restrict__ jtrs,
            const float* __restrict__ W0, const float* __restrict__ b0,
            const float* __restrict__ W1, const float* __restrict__ b1,
            const float* __restrict__ W2, const float* __restrict__ b2,
            float* __restrict__ out)
{
    extern __shared__ u64t sm[];
    float* stash = (float*)(sm + SM_U64);
    const int tid = threadIdx.x;

    // ---- prologue A: pack weights as row-pairs ----
    for (int i = tid; i < 24*19*10; i += 128) {
        int rp = i % 10; int t = i / 10; int k = t % 19; int j = t / 19;
        int r = 2*rp;
        float lo = W1[(j*19 + r)*19 + k];
        float hi = (r + 1 < 19) ? W1[(j*19 + r + 1)*19 + k] : 0.f;
        sm[OW1 + i] = pk2(lo, hi);
    }
    for (int i = tid; i < 24*20*3; i += 128) {
        int dp = i % 3; int t = i / 3; int k = t % 20; int j = t / 20;
        float lo, hi;
        if (k < 19) { lo = W2[(j*6 + 2*dp)*19 + k]; hi = W2[(j*6 + 2*dp + 1)*19 + k]; }
        else        { lo = b2[j*6 + 2*dp];          hi = b2[j*6 + 2*dp + 1]; }
        sm[OW2 + i] = pk2(lo, hi);
    }
    for (int i = tid; i < 288*3; i += 128) {
        int dp = i % 3; int k = i / 3;
        sm[OW0 + i] = pk2(W0[(2*dp)*288 + k], W0[(2*dp + 1)*288 + k]);
    }
    for (int i = tid; i < 24*10; i += 128) {
        int rp = i % 10; int j = i / 10;
        int r = 2*rp;
        float lo = b1[j*19 + r];
        float hi = (r + 1 < 19) ? b1[j*19 + r + 1] : 0.f;
        sm[OB1 + i] = pk2(lo, hi);
    }
    if (tid < 3) sm[OB0 + tid] = pk2(b0[2*tid], b0[2*tid + 1]);

    // ---- prologue B: coalesced staging of this CTA's 128 elements into stash ----
    {
        const float4* gr4 = (const float4*)(rots + (size_t)blockIdx.x * 128 * 216);
        const float4* gt4 = (const float4*)(jtrs + (size_t)blockIdx.x * 128 * 72);
#pragma unroll 6
        for (int i = 0; i < 54; ++i) {                  // rots: 6912 float4
            int G = i*128 + tid;
            float4 v = gr4[G];
            int e = G / 54, f4 = G % 54;
            int base = (4*f4)*STASH_STRIDE + e;
            stash[base                  ] = v.x;
            stash[base +   STASH_STRIDE] = v.y;
            stash[base + 2*STASH_STRIDE] = v.z;
            stash[base + 3*STASH_STRIDE] = v.w;
        }
#pragma unroll 6
        for (int i = 0; i < 18; ++i) {                  // jtrs: 2304 float4
            int G = i*128 + tid;
            float4 v = gt4[G];
            int e = G / 18, f4 = G % 18;
            int base = (216 + 4*f4)*STASH_STRIDE + e;
            stash[base                  ] = v.x;
            stash[base +   STASH_STRIDE] = v.y;
            stash[base + 2*STASH_STRIDE] = v.z;
            stash[base + 3*STASH_STRIDE] = v.w;
        }
    }
    __syncthreads();

    float* ob = out + ((size_t)blockIdx.x * 128 + tid) * 144;

    // ---- pass 1: gfeat = W0 @ x + b0 (x from stash, conflict-free LDS) ----
    u64t g[3];
    g[0] = sm[OB0 + 0]; g[1] = sm[OB0 + 1]; g[2] = sm[OB0 + 2];
#pragma unroll 8
    for (int kp = 0; kp < 144; ++kp) {
        int k0 = 2*kp;
        float v0 = stash[k0*STASH_STRIDE + tid];
        float v1 = stash[(k0 + 1)*STASH_STRIDE + tid];
        const ulonglong2* wp = (const ulonglong2*)(sm + OW0 + k0*3);
        ulonglong2 p0 = wp[0], p1 = wp[1], p2 = wp[2];
        u64t x0 = pk2(v0, v0);
        u64t x1 = pk2(v1, v1);
        g[0] = fma2(x0, p0.x, g[0]);
        g[1] = fma2(x0, p0.y, g[1]);
        g[2] = fma2(x0, p1.x, g[2]);
        g[0] = fma2(x1, p1.y, g[0]);
        g[1] = fma2(x1, p2.x, g[1]);
        g[2] = fma2(x1, p2.y, g[2]);
    }

    // ---- pass 2: joint chain, 4-slot liveness allocation ----
    u64t fslot[4][3];
    float jx[4], jy[4], jz[4];

    do_joint< 0,-1,0>(stash, tid, ob, sm, fslot, jx, jy, jz, g);
    do_joint< 1, 0,1>(stash, tid, ob, sm, fslot, jx, jy, jz, g);
    do_joint< 2, 0,2>(stash, tid, ob, sm, fslot, jx, jy, jz, g);
    do_joint< 3, 0,3>(stash, tid, ob, sm, fslot, jx, jy, jz, g);
    do_joint< 4, 1,0>(stash, tid, ob, sm, fslot, jx, jy, jz, g);
    do_joint< 5, 2,1>(stash, tid, ob, sm, fslot, jx, jy, jz, g);
    do_joint< 6, 3,2>(stash, tid, ob, sm, fslot, jx, jy, jz, g);
    do_joint< 7, 0,3>(stash, tid, ob, sm, fslot, jx, jy, jz, g);
    do_joint< 8, 1,0>(stash, tid, ob, sm, fslot, jx, jy, jz, g);
    do_joint< 9, 2,1>(stash, tid, ob, sm, fslot, jx, jy, jz, g);
    do_joint<10, 3,2>(stash, tid, ob, sm, fslot, jx, jy, jz, g);
    do_joint<11, 0,2>(stash, tid, ob, sm, fslot, jx, jy, jz, g);
    do_joint<12, 1,2>(stash, tid, ob, sm, fslot, jx, jy, jz, g);
    do_joint<13, 1,0>(stash, tid, ob, sm, fslot, jx, jy, jz, g);
    do_joint<14, 1,3>(stash, tid, ob, sm, fslot, jx, jy, jz, g);
    do_joint<15, 2,1>(stash, tid, ob, sm, fslot, jx, jy, jz, g);
    do_joint<16, 0,1>(stash, tid, ob, sm, fslot, jx, jy, jz, g);
    do_joint<17, 3,0>(stash, tid, ob, sm, fslot, jx, jy, jz, g);
    do_joint<18, 1,3>(stash, tid, ob, sm, fslot, jx, jy, jz, g);
    do_joint<19, 0,1>(stash, tid, ob, sm, fslot, jx, jy, jz, g);
    do_joint<20, 3,0>(stash, tid, ob, sm, fslot, jx, jy, jz, g);
    do_joint<21, 1,3>(stash, tid, ob, sm, fslot, jx, jy, jz, g);
    do_joint<22, 0,1>(stash, tid, ob, sm, fslot, jx, jy, jz, g);
    do_joint<23, 3,0>(stash, tid, ob, sm, fslot, jx, jy, jz, g);
}

extern "C" void kernel_launch(void* const* d_in, const int* in_sizes, int n_in,
                              void* d_out, int out_size) {
    (void)n_in; (void)out_size;
    const float* rots = (const float*)d_in[0];
    const float* jtrs = (const float*)d_in[1];
    const float* W0   = (const float*)d_in[2];
    const float* b0   = (const float*)d_in[3];
    const float* W1   = (const float*)d_in[4];
    const float* b1   = (const float*)d_in[5];
    const float* W2   = (const float*)d_in[6];
    const float* b2   = (const float*)d_in[7];
    float* out = (float*)d_out;

    int n = in_sizes[0] / 216;        // B (131072 -> divisible by 128)
    int grid = n / 128;

    cudaFuncSetAttribute(pose_kernel, cudaFuncAttributeMaxDynamicSharedMemorySize, SMEM_BYTES);
    pose_kernel<<<grid, 128, SMEM_BYTES>>>(rots, jtrs, W0, b0, W1, b1, W2, b2, out);
}